// round 9
// baseline (speedup 1.0000x reference)
#include <cuda_runtime.h>
#include <cuda_bf16.h>
#include <math.h>

#define N0   120000
#define N1V  12000
#define N2V  1024
#define E1N  300000
#define E2N  10240
#define F_IN 602
#define H1N  8
#define C1N  8
#define D1   64
#define NCLS 41
#define NEG  0.2f

#define EL1  (E1N + N1V)   // 312000
#define EL2  (E2N + N2V)   // 11264
#define KPAD 608
#define CAP  128

// ---------------- scratch ----------------
__device__ float          g_Hfull[(size_t)N0 * D1];
__device__ float          g_as1[N0 * H1N];
__device__ float          g_ad1[N1V * H1N];
__device__ float          g_out1[N1V * D1];
__device__ float          g_H2[N1V * NCLS];
__device__ float          g_as2[N1V];
__device__ float          g_ad2[N2V];
__device__ float          g_s2[N2V];
__device__ float          g_out2[N2V * NCLS];
__device__ __nv_bfloat16  g_W1h[D1 * KPAD];
__device__ __nv_bfloat16  g_W1l[D1 * KPAD];
__device__ int2           g_e2sd[EL2];
__device__ int            g_cnt1[N1V];
__device__ int            g_nbr1[N1V * CAP];

// ================= launch 1: zero =================
__global__ void k_zero() {
    int i = blockIdx.x * blockDim.x + threadIdx.x;
    if (i < N1V) g_cnt1[i] = 0;
    if (i < N2V * NCLS) g_out2[i] = 0.f;
    if (i < N2V) g_s2[i] = 0.f;
}

// ================= launch 2: W1 bf16 hi/lo split =================
__global__ void k_prep_w(const float* __restrict__ W1) {
    int nt = gridDim.x * blockDim.x;
    for (int i = blockIdx.x * blockDim.x + threadIdx.x; i < D1 * KPAD; i += nt) {
        int n = i / KPAD, k = i - n * KPAD;
        float v = (k < F_IN) ? W1[(size_t)k * D1 + n] : 0.f;
        __nv_bfloat16 h = __float2bfloat16(v);
        g_W1h[i] = h;
        g_W1l[i] = __float2bfloat16(v - __bfloat162float(h));
    }
}

// ================= launch 3: edge decode + bucket scatter =================
__global__ void k_prep_e(const void* e1, const void* e2) {
    __shared__ int se64;
    if (threadIdx.x == 0) {
        const long long* p = (const long long*)e1;
        bool ok = true;
        for (int i = 0; i < 16; i++) {
            long long v = p[i];
            if (v < 0 || v >= (long long)N0) { ok = false; break; }
        }
        se64 = ok ? 1 : 0;
    }
    __syncthreads();
    int e64 = se64;
    int nt = gridDim.x * blockDim.x;
    int t0 = blockIdx.x * blockDim.x + threadIdx.x;

    for (int e = t0; e < EL1; e += nt) {
        int s, d;
        if (e < E1N) {
            if (e64) {
                s = (int)((const long long*)e1)[e];
                d = (int)((const long long*)e1)[E1N + e];
            } else {
                s = ((const int*)e1)[e];
                d = ((const int*)e1)[E1N + e];
            }
        } else { s = d = e - E1N; }
        int pos = atomicAdd(&g_cnt1[d], 1);
        if (pos < CAP) g_nbr1[d * CAP + pos] = s;
    }
    for (int e = t0; e < EL2; e += nt) {
        int s, d;
        if (e < E2N) {
            if (e64) {
                s = (int)((const long long*)e2)[e];
                d = (int)((const long long*)e2)[E2N + e];
            } else {
                s = ((const int*)e2)[e];
                d = ((const int*)e2)[E2N + e];
            }
        } else { s = d = e - E2N; }
        g_e2sd[e] = make_int2(s, d);
    }
}

// ================= launch 4: GEMM1 — async staging pipeline, 3 CTA/SM =================
#define KC      32
#define NCHUNK  19
#define SRB     80
#define STG0    0          // fp32 staging chunk buf0: 128*32*4 = 16384
#define STG1    16384
#define OFF_AH  32768      // 128*80 = 10240
#define OFF_AL  43008
#define OFF_B0  53248      // hi 5120 + lo 5120
#define OFF_B1  63488
#define SMEM_G1 73728      // 72 KB -> 3 CTAs/SM
#define CS_STRIDE 72

__device__ __forceinline__ unsigned smem_u32(const void* p) {
    unsigned a;
    asm("{ .reg .u64 t; cvta.to.shared.u64 t, %1; cvt.u32.u64 %0, t; }" : "=r"(a) : "l"(p));
    return a;
}

__device__ __forceinline__ void cvt2(float2 v, unsigned& hp, unsigned& lp) {
    __nv_bfloat16 hx = __float2bfloat16(v.x), hy = __float2bfloat16(v.y);
    float rx = v.x - __bfloat162float(hx), ry = v.y - __bfloat162float(hy);
    __nv_bfloat16 lx = __float2bfloat16(rx), ly = __float2bfloat16(ry);
    hp = ((unsigned)__bfloat16_as_ushort(hy) << 16) | __bfloat16_as_ushort(hx);
    lp = ((unsigned)__bfloat16_as_ushort(ly) << 16) | __bfloat16_as_ushort(lx);
}

__device__ __forceinline__ void mma_bf16(float* c, const unsigned* a, unsigned b0, unsigned b1) {
    asm volatile(
        "mma.sync.aligned.m16n8k16.row.col.f32.bf16.bf16.f32 "
        "{%0,%1,%2,%3}, {%4,%5,%6,%7}, {%8,%9}, {%0,%1,%2,%3};"
        : "+f"(c[0]), "+f"(c[1]), "+f"(c[2]), "+f"(c[3])
        : "r"(a[0]), "r"(a[1]), "r"(a[2]), "r"(a[3]), "r"(b0), "r"(b1));
}

__device__ __forceinline__ void ldm4(unsigned addr, unsigned* r) {
    asm volatile("ldmatrix.sync.aligned.m8n8.x4.shared.b16 {%0,%1,%2,%3}, [%4];"
                 : "=r"(r[0]), "=r"(r[1]), "=r"(r[2]), "=r"(r[3]) : "r"(addr));
}

__device__ __forceinline__ void cpa16(unsigned dst, const void* src) {
    asm volatile("cp.async.cg.shared.global [%0], [%1], 16;" :: "r"(dst), "l"(src));
}
__device__ __forceinline__ void cpa8(unsigned dst, const void* src) {
    asm volatile("cp.async.ca.shared.global [%0], [%1], 8;" :: "r"(dst), "l"(src));
}

// A chunk: thread t covers row r=t>>1, half h=t&1 (16 floats) via 8x cp.async.8
__device__ __forceinline__ void issue_A(unsigned stg, const float* x, int row0, int t, int k0) {
    int r = t >> 1, h = t & 1;
    const float* src = x + (size_t)(row0 + r) * F_IN + k0 + h * 16;
    unsigned dst = stg + (unsigned)(r * 32 + h * 16) * 4;
    bool rowok = (row0 + r < N0);
#pragma unroll
    for (int q = 0; q < 8; q++) {
        int gk = k0 + h * 16 + 2 * q;
        if (rowok && gk + 1 < F_IN) cpa8(dst + q * 8, src + 2 * q);
        // else: stale staging bytes -> multiplied by zero-padded B rows -> contributes 0
    }
}

__device__ __forceinline__ void issue_B(unsigned bbase, int t, int k0) {
    int bn = t >> 2, bq = t & 3;
    unsigned dsto = bbase + (unsigned)(bn * SRB + bq * 16);
    int srco = bn * KPAD + k0 + bq * 8;
    cpa16(dsto, (const void*)(g_W1h + srco));
    cpa16(dsto + 5120, (const void*)(g_W1l + srco));
}

// fp32 staging -> bf16 hi/lo (thread converts exactly the bytes its cp.async wrote)
__device__ __forceinline__ void convertA(unsigned char* smem, unsigned stg_off, int t) {
    int r = t >> 1, h = t & 1;
    const float4* src = (const float4*)(smem + stg_off + (unsigned)(r * 32 + h * 16) * 4);
    unsigned* dsth = (unsigned*)(smem + OFF_AH + r * SRB) + h * 8;
    unsigned* dstl = (unsigned*)(smem + OFF_AL + r * SRB) + h * 8;
#pragma unroll
    for (int q = 0; q < 4; q++) {
        float4 v = src[q];
        unsigned hp, lp;
        cvt2(make_float2(v.x, v.y), hp, lp);
        dsth[q * 2] = hp; dstl[q * 2] = lp;
        cvt2(make_float2(v.z, v.w), hp, lp);
        dsth[q * 2 + 1] = hp; dstl[q * 2 + 1] = lp;
    }
}

__global__ void __launch_bounds__(256, 3)
k_gemm1_mma(const float* __restrict__ x,
            const float* __restrict__ a_src, const float* __restrict__ a_dst) {
    extern __shared__ unsigned char smem[];
    unsigned sb = smem_u32(smem);
    int t = threadIdx.x;
    int w = t >> 5, lane = t & 31;
    int g = lane >> 2, tig = lane & 3;
    int wm = w & 3, wn = w >> 2;
    int row0 = blockIdx.x * 128;

    float acc[2][4][4];
#pragma unroll
    for (int mi = 0; mi < 2; mi++)
#pragma unroll
        for (int ni = 0; ni < 4; ni++)
#pragma unroll
            for (int q = 0; q < 4; q++) acc[mi][ni][q] = 0.f;

    int arow = ((lane >> 3) & 1) * 8 + (lane & 7);
    unsigned a_loff = (unsigned)((wm * 32 + arow) * SRB + (lane >> 4) * 16);
    int brow = ((lane >> 4) << 3) + (lane & 7);
    unsigned b_loff = (unsigned)((wn * 32 + brow) * SRB + ((lane >> 3) & 1) * 16);

    // prologue: chunks 0 and 1 in flight (one commit group each)
    issue_A(sb + STG0, x, row0, t, 0);
    issue_B(sb + OFF_B0, t, 0);
    asm volatile("cp.async.commit_group;");
    issue_A(sb + STG1, x, row0, t, KC);
    issue_B(sb + OFF_B1, t, KC);
    asm volatile("cp.async.commit_group;");

    for (int c = 0; c < NCHUNK; c++) {
        int buf = c & 1;
        unsigned stg = sb + (buf ? STG1 : STG0);
        unsigned bbase = sb + (buf ? OFF_B1 : OFF_B0);

        asm volatile("cp.async.wait_group 1;");
        __syncthreads();                    // chunk c visible; Abf free (prev compute done)
        convertA(smem, buf ? STG1 : STG0, t);
        if (c + 2 < NCHUNK)                 // staging[buf] consumed by THIS thread already
            issue_A(stg, x, row0, t, (c + 2) * KC);
        __syncthreads();                    // Abf visible to all

        // compute: Abf (single) x B[buf]
        {
            unsigned abh = sb + OFF_AH + a_loff;
            unsigned abl = sb + OFF_AL + a_loff;
            unsigned bbh = bbase + b_loff;
            unsigned bbl = bbase + 5120 + b_loff;
#pragma unroll
            for (int kb = 0; kb < 2; kb++) {
                unsigned ko = kb * 32;
                unsigned ah[2][4], al[2][4], bh[2][4], bl[2][4];
#pragma unroll
                for (int mi = 0; mi < 2; mi++) {
                    ldm4(abh + mi * (16 * SRB) + ko, ah[mi]);
                    ldm4(abl + mi * (16 * SRB) + ko, al[mi]);
                }
#pragma unroll
                for (int nb = 0; nb < 2; nb++) {
                    ldm4(bbh + nb * (16 * SRB) + ko, bh[nb]);
                    ldm4(bbl + nb * (16 * SRB) + ko, bl[nb]);
                }
#pragma unroll
                for (int mi = 0; mi < 2; mi++)
#pragma unroll
                    for (int nb = 0; nb < 2; nb++) {
                        mma_bf16(acc[mi][nb * 2 + 0], ah[mi], bh[nb][0], bh[nb][1]);
                        mma_bf16(acc[mi][nb * 2 + 1], ah[mi], bh[nb][2], bh[nb][3]);
                        mma_bf16(acc[mi][nb * 2 + 0], al[mi], bh[nb][0], bh[nb][1]);
                        mma_bf16(acc[mi][nb * 2 + 1], al[mi], bh[nb][2], bh[nb][3]);
                        mma_bf16(acc[mi][nb * 2 + 0], ah[mi], bl[nb][0], bl[nb][1]);
                        mma_bf16(acc[mi][nb * 2 + 1], ah[mi], bl[nb][2], bl[nb][3]);
                    }
            }
        }
        __syncthreads();                    // everyone done reading B[buf]
        if (c + 2 < NCHUNK)
            issue_B(bbase, t, (c + 2) * KC);
        asm volatile("cp.async.commit_group;");  // one group per iteration (possibly empty)
    }

    // epilogue: stage C in smem, coalesced stores + fused logits
    float* Cs = (float*)smem;
    __syncthreads();
#pragma unroll
    for (int mi = 0; mi < 2; mi++)
#pragma unroll
        for (int ni = 0; ni < 4; ni++) {
            int r = wm * 32 + mi * 16 + g;
            int cc = wn * 32 + ni * 8 + tig * 2;
            Cs[r * CS_STRIDE + cc]           = acc[mi][ni][0];
            Cs[r * CS_STRIDE + cc + 1]       = acc[mi][ni][1];
            Cs[(r + 8) * CS_STRIDE + cc]     = acc[mi][ni][2];
            Cs[(r + 8) * CS_STRIDE + cc + 1] = acc[mi][ni][3];
        }
    __syncthreads();

#pragma unroll
    for (int it = 0; it < 8; it++) {
        int r = (t >> 4) + 16 * it;
        int c4 = (t & 15) * 4;
        if (row0 + r < N0) {
            float4 v = *(const float4*)(Cs + r * CS_STRIDE + c4);
            *(float4*)(g_Hfull + (size_t)(row0 + r) * D1 + c4) = v;
        }
    }
    if (t < 128) {
        int m = row0 + t;
        if (m < N0) {
            const float* rr = Cs + t * CS_STRIDE;
#pragma unroll
            for (int h = 0; h < H1N; h++) {
                float as = 0.f, ad = 0.f;
#pragma unroll
                for (int cc = 0; cc < C1N; cc++) {
                    float v = rr[h * C1N + cc];
                    as = fmaf(v, __ldg(&a_src[h * C1N + cc]), as);
                    ad = fmaf(v, __ldg(&a_dst[h * C1N + cc]), ad);
                }
                g_as1[m * H1N + h] = as;
                if (m < N1V) g_ad1[m * H1N + h] = ad;
            }
        }
    }
}

// ================= launch 5: fused layer-1 softmax + aggregate =================
#define EXS 9
__global__ void __launch_bounds__(256)
k_edge1_fused(const float* __restrict__ b1) {
    __shared__ float s_ex[8][CAP * EXS];
    __shared__ int   s_nbr[8][CAP];
    int wid = threadIdx.x >> 5, lane = threadIdx.x & 31;
    int node = blockIdx.x * 8 + wid;
    if (node >= N1V) return;
    int deg = g_cnt1[node];
    if (deg > CAP) deg = CAP;
    float* exs = s_ex[wid];
    int* nbs = s_nbr[wid];

    float4 adA = __ldg((const float4*)&g_ad1[node * 8]);
    float4 adB = __ldg((const float4*)&g_ad1[node * 8 + 4]);
    float sum[8] = {0.f, 0.f, 0.f, 0.f, 0.f, 0.f, 0.f, 0.f};

    for (int e = lane; e < deg; e += 32) {
        int s = __ldg(&g_nbr1[node * CAP + e]);
        nbs[e] = s;
        float4 sa = __ldg((const float4*)&g_as1[s * 8]);
        float4 sbv = __ldg((const float4*)&g_as1[s * 8 + 4]);
        float a[8] = { sa.x + adA.x, sa.y + adA.y, sa.z + adA.z, sa.w + adA.w,
                       sbv.x + adB.x, sbv.y + adB.y, sbv.z + adB.z, sbv.w + adB.w };
#pragma unroll
        for (int h = 0; h < 8; h++) {
            float v = a[h] > 0.f ? a[h] : NEG * a[h];
            float ex = expf(v);
            sum[h] += ex;
            exs[e * EXS + h] = ex;
        }
    }
    __syncwarp();
#pragma unroll
    for (int h = 0; h < 8; h++)
#pragma unroll
        for (int o = 16; o > 0; o >>= 1)
            sum[h] += __shfl_xor_sync(0xffffffffu, sum[h], o);

    int myh = lane >> 2;
    float myr = 1.f / (sum[myh] + 1e-16f);

    float ax = 0.f, ay = 0.f;
#pragma unroll 4
    for (int e = 0; e < deg; e++) {
        float wgt = exs[e * EXS + myh] * myr;
        int s = nbs[e];
        float2 hv = __ldg((const float2*)&g_Hfull[(size_t)s * D1 + 2 * lane]);
        ax = fmaf(wgt, hv.x, ax);
        ay = fmaf(wgt, hv.y, ay);
    }
    float bx = __ldg(&b1[2 * lane]), by = __ldg(&b1[2 * lane + 1]);
    float vx = ax + bx; vx = vx > 0.f ? vx : expm1f(vx);
    float vy = ay + by; vy = vy > 0.f ? vy : expm1f(vy);
    *(float2*)&g_out1[node * D1 + 2 * lane] = make_float2(vx, vy);
}

// ================= layer 2 =================
__global__ void k_gemm2(const float* __restrict__ W2) {
    __shared__ float Ws[D1 * NCLS];
    for (int i = threadIdx.x; i < D1 * NCLS; i += blockDim.x) Ws[i] = W2[i];
    __syncthreads();
    int t = blockIdx.x * blockDim.x + threadIdx.x;
    if (t >= N1V * NCLS) return;
    int row = t / NCLS, col = t - row * NCLS;
    const float* hr = g_out1 + row * D1;
    float acc = 0.f;
#pragma unroll
    for (int k = 0; k < D1; k++) acc = fmaf(hr[k], Ws[k * NCLS + col], acc);
    g_H2[t] = acc;
}

__global__ void k_att2(const float* __restrict__ a_src, const float* __restrict__ a_dst) {
    int i = blockIdx.x * blockDim.x + threadIdx.x;
    if (i >= N1V) return;
    const float* hp = g_H2 + i * NCLS;
    float as = 0.f;
#pragma unroll
    for (int c = 0; c < NCLS; c++) as += hp[c] * a_src[c];
    g_as2[i] = as;
    if (i < N2V) {
        float ad = 0.f;
#pragma unroll
        for (int c = 0; c < NCLS; c++) ad += hp[c] * a_dst[c];
        g_ad2[i] = ad;
    }
}

__global__ void k_edge2_sum() {
    int e = blockIdx.x * blockDim.x + threadIdx.x;
    if (e >= EL2) return;
    int2 sd = g_e2sd[e];
    float al = g_as2[sd.x] + g_ad2[sd.y];
    al = al > 0.f ? al : NEG * al;
    atomicAdd(&g_s2[sd.y], expf(al));
}

__global__ void k_edge2_agg() {
    int t = blockIdx.x * blockDim.x + threadIdx.x;
    if (t >= EL2 * NCLS) return;
    int e = t / NCLS, c = t - e * NCLS;
    int2 sd = g_e2sd[e];
    float al = g_as2[sd.x] + g_ad2[sd.y];
    al = al > 0.f ? al : NEG * al;
    float w = expf(al) / (g_s2[sd.y] + 1e-16f);
    atomicAdd(&g_out2[sd.y * NCLS + c], g_H2[sd.x * NCLS + c] * w);
}

__global__ void k_final(float* __restrict__ out, const float* __restrict__ b2) {
    int d = blockIdx.x;
    int lane = threadIdx.x;
    float v0 = (lane < NCLS) ? g_out2[d * NCLS + lane] + b2[lane] : -INFINITY;
    float v1 = (lane + 32 < NCLS) ? g_out2[d * NCLS + lane + 32] + b2[lane + 32] : -INFINITY;
    float m = fmaxf(v0, v1);
#pragma unroll
    for (int o = 16; o > 0; o >>= 1) m = fmaxf(m, __shfl_xor_sync(0xffffffffu, m, o));
    float s = ((lane < NCLS) ? expf(v0 - m) : 0.f) + ((lane + 32 < NCLS) ? expf(v1 - m) : 0.f);
#pragma unroll
    for (int o = 16; o > 0; o >>= 1) s += __shfl_xor_sync(0xffffffffu, s, o);
    float ls = m + logf(s);
    if (lane < NCLS) out[d * NCLS + lane] = v0 - ls;
    if (lane + 32 < NCLS) out[d * NCLS + lane + 32] = v1 - ls;
}

// ---------------- launch ----------------
extern "C" void kernel_launch(void* const* d_in, const int* in_sizes, int n_in,
                              void* d_out, int out_size) {
    const float* x = nullptr;
    const void* e1 = nullptr;
    const void* e2 = nullptr;
    const float *W1 = nullptr, *as1 = nullptr, *ad1 = nullptr, *b1 = nullptr;
    const float *W2 = nullptr, *as2 = nullptr, *ad2 = nullptr, *b2 = nullptr;

    for (int i = 0; i < n_in; i++) {
        switch (in_sizes[i]) {
            case N0 * F_IN:   x  = (const float*)d_in[i]; break;
            case 2 * E1N:     e1 = d_in[i]; break;
            case 2 * E2N:     e2 = d_in[i]; break;
            case F_IN * D1:
                W1  = (const float*)d_in[i];
                if (i + 3 < n_in) {
                    as1 = (const float*)d_in[i + 1];
                    ad1 = (const float*)d_in[i + 2];
                    b1  = (const float*)d_in[i + 3];
                }
                break;
            case D1 * NCLS:
                W2  = (const float*)d_in[i];
                if (i + 3 < n_in) {
                    as2 = (const float*)d_in[i + 1];
                    ad2 = (const float*)d_in[i + 2];
                    b2  = (const float*)d_in[i + 3];
                }
                break;
            default: break;
        }
    }

    float* out = (float*)d_out;
    const int TPB = 256;

    cudaFuncSetAttribute(k_gemm1_mma, cudaFuncAttributeMaxDynamicSharedMemorySize, SMEM_G1);

    k_zero<<<(N2V * NCLS + TPB - 1) / TPB, TPB>>>();                 // 1
    k_prep_w<<<160, TPB>>>(W1);                                       // 2
    k_prep_e<<<512, TPB>>>(e1, e2);                                   // 3
    k_gemm1_mma<<<(N0 + 127) / 128, TPB, SMEM_G1>>>(x, as1, ad1);     // 4 <- profiled
    k_edge1_fused<<<(N1V + 7) / 8, TPB>>>(b1);                        // 5
    k_gemm2<<<(N1V * NCLS + TPB - 1) / TPB, TPB>>>(W2);               // 6
    k_att2<<<(N1V + TPB - 1) / TPB, TPB>>>(as2, ad2);                 // 7
    k_edge2_sum<<<(EL2 + TPB - 1) / TPB, TPB>>>();                    // 8
    k_edge2_agg<<<(EL2 * NCLS + TPB - 1) / TPB, TPB>>>();             // 9
    k_final<<<N2V, 32>>>(out, b2);                                    // 10
}

// round 10
// speedup vs baseline: 1.8932x; 1.8932x over previous
#include <cuda_runtime.h>
#include <cuda_bf16.h>
#include <math.h>

#define N0   120000
#define N1V  12000
#define N2V  1024
#define E1N  300000
#define E2N  10240
#define F_IN 602
#define H1N  8
#define C1N  8
#define D1   64
#define NCLS 41
#define NEG  0.2f

#define EL1  (E1N + N1V)   // 312000
#define EL2  (E2N + N2V)   // 11264
#define KPAD 608
#define CAP  128

// ---------------- scratch ----------------
__device__ float          g_Hfull[(size_t)N0 * D1];
__device__ float          g_as1[N0 * H1N];
__device__ float          g_ad1[N1V * H1N];
__device__ float          g_out1[N1V * D1];
__device__ float          g_H2[N1V * NCLS];
__device__ float          g_as2[N1V];
__device__ float          g_ad2[N2V];
__device__ float          g_s2[N2V];
__device__ float          g_out2[N2V * NCLS];
__device__ __nv_bfloat16  g_W1h[D1 * KPAD];
__device__ __nv_bfloat16  g_W1l[D1 * KPAD];
__device__ int2           g_e2sd[EL2];
__device__ int            g_cnt1[N1V];
__device__ int            g_nbr1[N1V * CAP];

// ================= launch 1: zero =================
__global__ void k_zero() {
    int i = blockIdx.x * blockDim.x + threadIdx.x;
    if (i < N1V) g_cnt1[i] = 0;
    if (i < N2V * NCLS) g_out2[i] = 0.f;
    if (i < N2V) g_s2[i] = 0.f;
}

// ================= launch 2: W1 bf16 hi/lo split =================
__global__ void k_prep_w(const float* __restrict__ W1) {
    int nt = gridDim.x * blockDim.x;
    for (int i = blockIdx.x * blockDim.x + threadIdx.x; i < D1 * KPAD; i += nt) {
        int n = i / KPAD, k = i - n * KPAD;
        float v = (k < F_IN) ? W1[(size_t)k * D1 + n] : 0.f;
        __nv_bfloat16 h = __float2bfloat16(v);
        g_W1h[i] = h;
        g_W1l[i] = __float2bfloat16(v - __bfloat162float(h));
    }
}

// ================= launch 3: edge decode + bucket scatter =================
__global__ void k_prep_e(const void* e1, const void* e2) {
    __shared__ int se64;
    if (threadIdx.x == 0) {
        const long long* p = (const long long*)e1;
        bool ok = true;
        for (int i = 0; i < 16; i++) {
            long long v = p[i];
            if (v < 0 || v >= (long long)N0) { ok = false; break; }
        }
        se64 = ok ? 1 : 0;
    }
    __syncthreads();
    int e64 = se64;
    int nt = gridDim.x * blockDim.x;
    int t0 = blockIdx.x * blockDim.x + threadIdx.x;

    for (int e = t0; e < EL1; e += nt) {
        int s, d;
        if (e < E1N) {
            if (e64) {
                s = (int)((const long long*)e1)[e];
                d = (int)((const long long*)e1)[E1N + e];
            } else {
                s = ((const int*)e1)[e];
                d = ((const int*)e1)[E1N + e];
            }
        } else { s = d = e - E1N; }
        int pos = atomicAdd(&g_cnt1[d], 1);
        if (pos < CAP) g_nbr1[d * CAP + pos] = s;
    }
    for (int e = t0; e < EL2; e += nt) {
        int s, d;
        if (e < E2N) {
            if (e64) {
                s = (int)((const long long*)e2)[e];
                d = (int)((const long long*)e2)[E2N + e];
            } else {
                s = ((const int*)e2)[e];
                d = ((const int*)e2)[E2N + e];
            }
        } else { s = d = e - E2N; }
        g_e2sd[e] = make_int2(s, d);
    }
}

// ================= launch 4: GEMM1 (R7 structure, fast packed cvt) =================
#define KC      32
#define NCHUNK  19
#define SA_U32  20
#define SRB     80
#define OFF_AH  0
#define OFF_AL  10240
#define OFF_BH  20480
#define OFF_BL  25600
#define BUFB    30720
#define SMEM_G1 (2 * BUFB)
#define CS_STRIDE 72

__device__ __forceinline__ unsigned smem_u32(const void* p) {
    unsigned a;
    asm("{ .reg .u64 t; cvta.to.shared.u64 t, %1; cvt.u32.u64 %0, t; }" : "=r"(a) : "l"(p));
    return a;
}

// fast fp32x2 -> bf16x2 hi/lo split: 6 ops per 2 floats (same rn rounding as before)
__device__ __forceinline__ void cvt2(float2 v, unsigned& hp, unsigned& lp) {
    asm("cvt.rn.bf16x2.f32 %0, %1, %2;" : "=r"(hp) : "f"(v.y), "f"(v.x));  // hi pair: y->upper, x->lower
    float hx = __uint_as_float(hp << 16);
    float hy = __uint_as_float(hp & 0xffff0000u);
    float lx = v.x - hx, ly = v.y - hy;
    asm("cvt.rn.bf16x2.f32 %0, %1, %2;" : "=r"(lp) : "f"(ly), "f"(lx));
}

__device__ __forceinline__ void mma_bf16(float* c, const unsigned* a, unsigned b0, unsigned b1) {
    asm volatile(
        "mma.sync.aligned.m16n8k16.row.col.f32.bf16.bf16.f32 "
        "{%0,%1,%2,%3}, {%4,%5,%6,%7}, {%8,%9}, {%0,%1,%2,%3};"
        : "+f"(c[0]), "+f"(c[1]), "+f"(c[2]), "+f"(c[3])
        : "r"(a[0]), "r"(a[1]), "r"(a[2]), "r"(a[3]), "r"(b0), "r"(b1));
}

__device__ __forceinline__ void ldm4(unsigned addr, unsigned* r) {
    asm volatile("ldmatrix.sync.aligned.m8n8.x4.shared.b16 {%0,%1,%2,%3}, [%4];"
                 : "=r"(r[0]), "=r"(r[1]), "=r"(r[2]), "=r"(r[3]) : "r"(addr));
}

__device__ __forceinline__ void cpa16(unsigned dst, const void* src) {
    asm volatile("cp.async.cg.shared.global [%0], [%1], 16;" :: "r"(dst), "l"(src));
}

__global__ void __launch_bounds__(256, 2)
k_gemm1_mma(const float* __restrict__ x,
            const float* __restrict__ a_src, const float* __restrict__ a_dst) {
    extern __shared__ unsigned char smem[];
    unsigned sb = smem_u32(smem);
    int t = threadIdx.x;
    int w = t >> 5, lane = t & 31;
    int g = lane >> 2, tig = lane & 3;
    int wm = w & 3, wn = w >> 2;
    int row0 = blockIdx.x * 128;

    float acc[2][4][4];
#pragma unroll
    for (int mi = 0; mi < 2; mi++)
#pragma unroll
        for (int ni = 0; ni < 4; ni++)
#pragma unroll
            for (int q = 0; q < 4; q++) acc[mi][ni][q] = 0.f;

    int bn = t >> 2, bq = t & 3;
    unsigned bdst_off = bn * SRB + bq * 16;
    int bsrc_elem = bn * KPAD + bq * 8;

    int arow = ((lane >> 3) & 1) * 8 + (lane & 7);
    unsigned a_loff = (unsigned)((wm * 32 + arow) * SRB + (lane >> 4) * 16);
    int brow = ((lane >> 4) << 3) + (lane & 7);
    unsigned b_loff = (unsigned)((wn * 32 + brow) * SRB + ((lane >> 3) & 1) * 16);

    {
        unsigned* Ah = (unsigned*)(smem + OFF_AH);
        unsigned* Al = (unsigned*)(smem + OFF_AL);
#pragma unroll
        for (int j = 0; j < 8; j++) {
            int idx = t + 256 * j;
            int row = idx >> 4, kq = idx & 15;
            float2 v = make_float2(0.f, 0.f);
            if (row0 + row < N0)
                v = *(const float2*)(x + (size_t)(row0 + row) * F_IN + 2 * kq);
            unsigned hp, lp; cvt2(v, hp, lp);
            Ah[row * SA_U32 + kq] = hp; Al[row * SA_U32 + kq] = lp;
        }
        cpa16(sb + OFF_BH + bdst_off, (const void*)(g_W1h + bsrc_elem));
        cpa16(sb + OFF_BL + bdst_off, (const void*)(g_W1l + bsrc_elem));
        asm volatile("cp.async.commit_group;");
        asm volatile("cp.async.wait_group 0;");
    }
    __syncthreads();

    for (int c = 0; c < NCHUNK; c++) {
        int cur = c & 1, nxt = cur ^ 1;
        bool have_next = (c + 1 < NCHUNK);
        float2 av[8];
        if (have_next) {
            int k0 = (c + 1) * KC;
            int ksrc = bsrc_elem + k0;
            cpa16(sb + nxt * BUFB + OFF_BH + bdst_off, (const void*)(g_W1h + ksrc));
            cpa16(sb + nxt * BUFB + OFF_BL + bdst_off, (const void*)(g_W1l + ksrc));
            asm volatile("cp.async.commit_group;");
#pragma unroll
            for (int j = 0; j < 8; j++) {
                int idx = t + 256 * j;
                int row = idx >> 4, kq = idx & 15;
                int gk = k0 + 2 * kq;
                float2 v = make_float2(0.f, 0.f);
                if (row0 + row < N0 && gk < F_IN)
                    v = *(const float2*)(x + (size_t)(row0 + row) * F_IN + gk);
                av[j] = v;
            }
        }
        {
            unsigned abh = sb + cur * BUFB + OFF_AH + a_loff;
            unsigned abl = sb + cur * BUFB + OFF_AL + a_loff;
            unsigned bbh = sb + cur * BUFB + OFF_BH + b_loff;
            unsigned bbl = sb + cur * BUFB + OFF_BL + b_loff;
#pragma unroll
            for (int kb = 0; kb < 2; kb++) {
                unsigned ko = kb * 32;
                unsigned ah[2][4], al[2][4], bh[2][4], bl[2][4];
#pragma unroll
                for (int mi = 0; mi < 2; mi++) {
                    ldm4(abh + mi * (16 * SRB) + ko, ah[mi]);
                    ldm4(abl + mi * (16 * SRB) + ko, al[mi]);
                }
#pragma unroll
                for (int nb = 0; nb < 2; nb++) {
                    ldm4(bbh + nb * (16 * SRB) + ko, bh[nb]);
                    ldm4(bbl + nb * (16 * SRB) + ko, bl[nb]);
                }
#pragma unroll
                for (int mi = 0; mi < 2; mi++)
#pragma unroll
                    for (int nb = 0; nb < 2; nb++) {
                        mma_bf16(acc[mi][nb * 2 + 0], ah[mi], bh[nb][0], bh[nb][1]);
                        mma_bf16(acc[mi][nb * 2 + 1], ah[mi], bh[nb][2], bh[nb][3]);
                        mma_bf16(acc[mi][nb * 2 + 0], al[mi], bh[nb][0], bh[nb][1]);
                        mma_bf16(acc[mi][nb * 2 + 1], al[mi], bh[nb][2], bh[nb][3]);
                        mma_bf16(acc[mi][nb * 2 + 0], ah[mi], bl[nb][0], bl[nb][1]);
                        mma_bf16(acc[mi][nb * 2 + 1], ah[mi], bl[nb][2], bl[nb][3]);
                    }
            }
        }
        if (have_next) {
            unsigned* Ah = (unsigned*)(smem + nxt * BUFB + OFF_AH);
            unsigned* Al = (unsigned*)(smem + nxt * BUFB + OFF_AL);
#pragma unroll
            for (int j = 0; j < 8; j++) {
                int idx = t + 256 * j;
                int row = idx >> 4, kq = idx & 15;
                unsigned hp, lp; cvt2(av[j], hp, lp);
                Ah[row * SA_U32 + kq] = hp; Al[row * SA_U32 + kq] = lp;
            }
        }
        asm volatile("cp.async.wait_group 0;");
        __syncthreads();
    }

    float* Cs = (float*)smem;
#pragma unroll
    for (int mi = 0; mi < 2; mi++)
#pragma unroll
        for (int ni = 0; ni < 4; ni++) {
            int r = wm * 32 + mi * 16 + g;
            int cc = wn * 32 + ni * 8 + tig * 2;
            Cs[r * CS_STRIDE + cc]           = acc[mi][ni][0];
            Cs[r * CS_STRIDE + cc + 1]       = acc[mi][ni][1];
            Cs[(r + 8) * CS_STRIDE + cc]     = acc[mi][ni][2];
            Cs[(r + 8) * CS_STRIDE + cc + 1] = acc[mi][ni][3];
        }
    __syncthreads();

#pragma unroll
    for (int it = 0; it < 8; it++) {
        int r = (t >> 4) + 16 * it;
        int c4 = (t & 15) * 4;
        if (row0 + r < N0) {
            float4 v = *(const float4*)(Cs + r * CS_STRIDE + c4);
            *(float4*)(g_Hfull + (size_t)(row0 + r) * D1 + c4) = v;
        }
    }
    if (t < 128) {
        int m = row0 + t;
        if (m < N0) {
            const float* rr = Cs + t * CS_STRIDE;
#pragma unroll
            for (int h = 0; h < H1N; h++) {
                float as = 0.f, ad = 0.f;
#pragma unroll
                for (int cc = 0; cc < C1N; cc++) {
                    float v = rr[h * C1N + cc];
                    as = fmaf(v, __ldg(&a_src[h * C1N + cc]), as);
                    ad = fmaf(v, __ldg(&a_dst[h * C1N + cc]), ad);
                }
                g_as1[m * H1N + h] = as;
                if (m < N1V) g_ad1[m * H1N + h] = ad;
            }
        }
    }
}

// ================= launch 5: fused layer-1 softmax + aggregate =================
#define EXS 9
__global__ void __launch_bounds__(256)
k_edge1_fused(const float* __restrict__ b1) {
    __shared__ float s_ex[8][CAP * EXS];
    __shared__ int   s_nbr[8][CAP];
    int wid = threadIdx.x >> 5, lane = threadIdx.x & 31;
    int node = blockIdx.x * 8 + wid;
    if (node >= N1V) return;
    int deg = g_cnt1[node];
    if (deg > CAP) deg = CAP;
    float* exs = s_ex[wid];
    int* nbs = s_nbr[wid];

    float4 adA = __ldg((const float4*)&g_ad1[node * 8]);
    float4 adB = __ldg((const float4*)&g_ad1[node * 8 + 4]);
    float sum[8] = {0.f, 0.f, 0.f, 0.f, 0.f, 0.f, 0.f, 0.f};

    for (int e = lane; e < deg; e += 32) {
        int s = __ldg(&g_nbr1[node * CAP + e]);
        nbs[e] = s;
        float4 sa = __ldg((const float4*)&g_as1[s * 8]);
        float4 sbv = __ldg((const float4*)&g_as1[s * 8 + 4]);
        float a[8] = { sa.x + adA.x, sa.y + adA.y, sa.z + adA.z, sa.w + adA.w,
                       sbv.x + adB.x, sbv.y + adB.y, sbv.z + adB.z, sbv.w + adB.w };
#pragma unroll
        for (int h = 0; h < 8; h++) {
            float v = a[h] > 0.f ? a[h] : NEG * a[h];
            float ex = expf(v);
            sum[h] += ex;
            exs[e * EXS + h] = ex;
        }
    }
    __syncwarp();
#pragma unroll
    for (int h = 0; h < 8; h++)
#pragma unroll
        for (int o = 16; o > 0; o >>= 1)
            sum[h] += __shfl_xor_sync(0xffffffffu, sum[h], o);

    int myh = lane >> 2;
    float myr = 1.f / (sum[myh] + 1e-16f);

    float ax = 0.f, ay = 0.f;
#pragma unroll 4
    for (int e = 0; e < deg; e++) {
        float wgt = exs[e * EXS + myh] * myr;
        int s = nbs[e];
        float2 hv = __ldg((const float2*)&g_Hfull[(size_t)s * D1 + 2 * lane]);
        ax = fmaf(wgt, hv.x, ax);
        ay = fmaf(wgt, hv.y, ay);
    }
    float bx = __ldg(&b1[2 * lane]), by = __ldg(&b1[2 * lane + 1]);
    float vx = ax + bx; vx = vx > 0.f ? vx : expm1f(vx);
    float vy = ay + by; vy = vy > 0.f ? vy : expm1f(vy);
    *(float2*)&g_out1[node * D1 + 2 * lane] = make_float2(vx, vy);
}

// ================= layer 2 =================
__global__ void k_gemm2(const float* __restrict__ W2) {
    __shared__ float Ws[D1 * NCLS];
    for (int i = threadIdx.x; i < D1 * NCLS; i += blockDim.x) Ws[i] = W2[i];
    __syncthreads();
    int t = blockIdx.x * blockDim.x + threadIdx.x;
    if (t >= N1V * NCLS) return;
    int row = t / NCLS, col = t - row * NCLS;
    const float* hr = g_out1 + row * D1;
    float acc = 0.f;
#pragma unroll
    for (int k = 0; k < D1; k++) acc = fmaf(hr[k], Ws[k * NCLS + col], acc);
    g_H2[t] = acc;
}

__global__ void k_att2(const float* __restrict__ a_src, const float* __restrict__ a_dst) {
    int i = blockIdx.x * blockDim.x + threadIdx.x;
    if (i >= N1V) return;
    const float* hp = g_H2 + i * NCLS;
    float as = 0.f;
#pragma unroll
    for (int c = 0; c < NCLS; c++) as += hp[c] * a_src[c];
    g_as2[i] = as;
    if (i < N2V) {
        float ad = 0.f;
#pragma unroll
        for (int c = 0; c < NCLS; c++) ad += hp[c] * a_dst[c];
        g_ad2[i] = ad;
    }
}

__global__ void k_edge2_sum() {
    int e = blockIdx.x * blockDim.x + threadIdx.x;
    if (e >= EL2) return;
    int2 sd = g_e2sd[e];
    float al = g_as2[sd.x] + g_ad2[sd.y];
    al = al > 0.f ? al : NEG * al;
    atomicAdd(&g_s2[sd.y], expf(al));
}

__global__ void k_edge2_agg() {
    int t = blockIdx.x * blockDim.x + threadIdx.x;
    if (t >= EL2 * NCLS) return;
    int e = t / NCLS, c = t - e * NCLS;
    int2 sd = g_e2sd[e];
    float al = g_as2[sd.x] + g_ad2[sd.y];
    al = al > 0.f ? al : NEG * al;
    float w = expf(al) / (g_s2[sd.y] + 1e-16f);
    atomicAdd(&g_out2[sd.y * NCLS + c], g_H2[sd.x * NCLS + c] * w);
}

__global__ void k_final(float* __restrict__ out, const float* __restrict__ b2) {
    int d = blockIdx.x;
    int lane = threadIdx.x;
    float v0 = (lane < NCLS) ? g_out2[d * NCLS + lane] + b2[lane] : -INFINITY;
    float v1 = (lane + 32 < NCLS) ? g_out2[d * NCLS + lane + 32] + b2[lane + 32] : -INFINITY;
    float m = fmaxf(v0, v1);
#pragma unroll
    for (int o = 16; o > 0; o >>= 1) m = fmaxf(m, __shfl_xor_sync(0xffffffffu, m, o));
    float s = ((lane < NCLS) ? expf(v0 - m) : 0.f) + ((lane + 32 < NCLS) ? expf(v1 - m) : 0.f);
#pragma unroll
    for (int o = 16; o > 0; o >>= 1) s += __shfl_xor_sync(0xffffffffu, s, o);
    float ls = m + logf(s);
    if (lane < NCLS) out[d * NCLS + lane] = v0 - ls;
    if (lane + 32 < NCLS) out[d * NCLS + lane + 32] = v1 - ls;
}

// ---------------- launch ----------------
extern "C" void kernel_launch(void* const* d_in, const int* in_sizes, int n_in,
                              void* d_out, int out_size) {
    const float* x = nullptr;
    const void* e1 = nullptr;
    const void* e2 = nullptr;
    const float *W1 = nullptr, *as1 = nullptr, *ad1 = nullptr, *b1 = nullptr;
    const float *W2 = nullptr, *as2 = nullptr, *ad2 = nullptr, *b2 = nullptr;

    for (int i = 0; i < n_in; i++) {
        switch (in_sizes[i]) {
            case N0 * F_IN:   x  = (const float*)d_in[i]; break;
            case 2 * E1N:     e1 = d_in[i]; break;
            case 2 * E2N:     e2 = d_in[i]; break;
            case F_IN * D1:
                W1  = (const float*)d_in[i];
                if (i + 3 < n_in) {
                    as1 = (const float*)d_in[i + 1];
                    ad1 = (const float*)d_in[i + 2];
                    b1  = (const float*)d_in[i + 3];
                }
                break;
            case D1 * NCLS:
                W2  = (const float*)d_in[i];
                if (i + 3 < n_in) {
                    as2 = (const float*)d_in[i + 1];
                    ad2 = (const float*)d_in[i + 2];
                    b2  = (const float*)d_in[i + 3];
                }
                break;
            default: break;
        }
    }

    float* out = (float*)d_out;
    const int TPB = 256;

    cudaFuncSetAttribute(k_gemm1_mma, cudaFuncAttributeMaxDynamicSharedMemorySize, SMEM_G1);

    k_zero<<<(N2V * NCLS + TPB - 1) / TPB, TPB>>>();                 // 1
    k_prep_w<<<160, TPB>>>(W1);                                       // 2
    k_prep_e<<<512, TPB>>>(e1, e2);                                   // 3
    k_gemm1_mma<<<(N0 + 127) / 128, TPB, SMEM_G1>>>(x, as1, ad1);     // 4 <- profiled
    k_edge1_fused<<<(N1V + 7) / 8, TPB>>>(b1);                        // 5
    k_gemm2<<<(N1V * NCLS + TPB - 1) / TPB, TPB>>>(W2);               // 6
    k_att2<<<(N1V + TPB - 1) / TPB, TPB>>>(as2, ad2);                 // 7
    k_edge2_sum<<<(EL2 + TPB - 1) / TPB, TPB>>>();                    // 8
    k_edge2_agg<<<(EL2 * NCLS + TPB - 1) / TPB, TPB>>>();             // 9
    k_final<<<N2V, 32>>>(out, b2);                                    // 10
}